// round 1
// baseline (speedup 1.0000x reference)
#include <cuda_runtime.h>

// Problem constants (fixed by the dataset)
#define BB    16
#define NCAM  6
#define PP    70000
#define HH    112
#define WW    200
#define BSN   (BB * NCAM)      // 96
#define HW    (HH * WW)        // 22400
#define BEV   200              // bev_side

// ---------------- device scratch (static: no allocation allowed) -----------
__device__ int    g_winner[BSN * HW];        // 8.6 MB   winner point index per cell (-1 = none)
__device__ float2 g_scratch[BSN * PP];       // 53.8 MB  (depth, vilu) per (camera, point)
__device__ float  g_cam[BSN][12];            // per camera: rows 0..2 of K4 @ Einv
__device__ float  g_invV[BB][16];            // per batch: inv(view)

// ---------------- kernel 0: reset winner grid ------------------------------
__global__ void k_init_winner() {
    int i = blockIdx.x * blockDim.x + threadIdx.x;
    if (i < BSN * HW) g_winner[i] = -1;
}

// ---------------- 4x4 inverse (adjugate, row-major) -------------------------
__device__ void inv4x4(const float* m, float* inv) {
    float a00=m[0], a01=m[1], a02=m[2], a03=m[3];
    float a10=m[4], a11=m[5], a12=m[6], a13=m[7];
    float a20=m[8], a21=m[9], a22=m[10],a23=m[11];
    float a30=m[12],a31=m[13],a32=m[14],a33=m[15];
    float b00=a00*a11-a01*a10, b01=a00*a12-a02*a10, b02=a00*a13-a03*a10;
    float b03=a01*a12-a02*a11, b04=a01*a13-a03*a11, b05=a02*a13-a03*a12;
    float b06=a20*a31-a21*a30, b07=a20*a32-a22*a30, b08=a20*a33-a23*a30;
    float b09=a21*a32-a22*a31, b10=a21*a33-a23*a31, b11=a22*a33-a23*a32;
    float det = b00*b11 - b01*b10 + b02*b09 + b03*b08 - b04*b07 + b05*b06;
    float id = 1.0f / det;
    inv[0]  = ( a11*b11 - a12*b10 + a13*b09)*id;
    inv[1]  = (-a01*b11 + a02*b10 - a03*b09)*id;
    inv[2]  = ( a31*b05 - a32*b04 + a33*b03)*id;
    inv[3]  = (-a21*b05 + a22*b04 - a23*b03)*id;
    inv[4]  = (-a10*b11 + a12*b08 - a13*b07)*id;
    inv[5]  = ( a00*b11 - a02*b08 + a03*b07)*id;
    inv[6]  = (-a30*b05 + a32*b02 - a33*b01)*id;
    inv[7]  = ( a20*b05 - a22*b02 + a23*b01)*id;
    inv[8]  = ( a10*b10 - a11*b08 + a13*b06)*id;
    inv[9]  = (-a00*b10 + a01*b08 - a03*b06)*id;
    inv[10] = ( a30*b04 - a31*b02 + a33*b00)*id;
    inv[11] = (-a20*b04 + a21*b02 - a23*b00)*id;
    inv[12] = (-a10*b09 + a11*b07 - a12*b06)*id;
    inv[13] = ( a00*b09 - a01*b07 + a02*b06)*id;
    inv[14] = (-a30*b03 + a31*b01 - a32*b00)*id;
    inv[15] = ( a20*b03 - a21*b01 + a22*b00)*id;
}

// ---------------- kernel 1: per-camera / per-batch matrix precompute --------
__global__ void k_precompute(const float* __restrict__ E4,   // (B,S,N,4,4)
                             const float* __restrict__ K3,   // (B,S,N,3,3)
                             const float* __restrict__ V4)   // (B,1,1,4,4)
{
    int t = threadIdx.x;
    if (t < BSN) {
        const float* e = E4 + t * 16;
        const float* k = K3 + t * 9;
        // Einv rotation = R^T ; Einv translation = -R^T t
        // Einv row i (i=0..2) = [ e[0*4+i], e[1*4+i], e[2*4+i], ti ]
        float Ei[3][4];
        #pragma unroll
        for (int i = 0; i < 3; i++) {
            float r0 = e[0*4 + i], r1 = e[1*4 + i], r2 = e[2*4 + i];
            Ei[i][0] = r0; Ei[i][1] = r1; Ei[i][2] = r2;
            Ei[i][3] = -(r0 * e[3] + r1 * e[7] + r2 * e[11]);
        }
        const float sx = 0.25f, sy = 0.25f;
        float f0 = k[0] * sx, c0 = k[2] * sx;   // fx*sx, cx*sx
        float f1 = k[4] * sy, c1 = k[5] * sy;   // fy*sy, cy*sy
        float* A = g_cam[t];
        #pragma unroll
        for (int j = 0; j < 4; j++) {
            A[0 + j] = f0 * Ei[0][j] + c0 * Ei[2][j];  // pixel row 0
            A[4 + j] = f1 * Ei[1][j] + c1 * Ei[2][j];  // pixel row 1
            A[8 + j] = Ei[2][j];                        // z row (== normalizer row)
        }
    } else if (t >= 96 && t < 96 + BB) {
        int b = t - 96;
        inv4x4(V4 + b * 16, g_invV[b]);
    }
}

// ---------------- kernel 2: per-point projection + winner scatter ----------
__global__ void __launch_bounds__(256)
k_points(const float* __restrict__ pcloud)   // (B,1,1,P,4)
{
    int idx = blockIdx.x * blockDim.x + threadIdx.x;
    if (idx >= BB * PP) return;               // exact grid: no partial warps
    int b = idx / PP;
    int p = idx - b * PP;

    float4 pt = reinterpret_cast<const float4*>(pcloud)[idx];
    const float* iv = g_invV[b];
    float w0 = iv[0]*pt.x + iv[1]*pt.y + iv[2] *pt.z + iv[3];
    float w1 = iv[4]*pt.x + iv[5]*pt.y + iv[6] *pt.z + iv[7];
    float w2 = iv[8]*pt.x + iv[9]*pt.y + iv[10]*pt.z + iv[11];
    float ilu = pt.w;
    int lane = threadIdx.x & 31;

    #pragma unroll
    for (int n = 0; n < NCAM; n++) {
        int bn = b * NCAM + n;
        const float* A = g_cam[bn];
        float px = A[0]*w0 + A[1]*w1 + A[2] *w2 + A[3];
        float py = A[4]*w0 + A[5]*w1 + A[6] *w2 + A[7];
        float z  = A[8]*w0 + A[9]*w1 + A[10]*w2 + A[11];

        float denom = fmaxf(z, 1e-6f);
        float x_ = px / denom;
        float y_ = py / denom;

        bool v = (x_ > -0.5f) & (x_ < (float)WW - 0.5f) &
                 (y_ > -0.5f) & (y_ < (float)HH - 0.5f) & (z > 0.0f);
        float valid = v ? 1.0f : 0.0f;
        float depth = fminf(fmaxf(z, 0.0f), (float)(BEV/2 - 1)) * valid;
        float vilu  = fminf(fmaxf(ilu * valid, 0.0f), 255.0f);

        int ym = (int)fminf(fmaxf(y_, 0.0f), (float)(HH - 1));
        int xm = (int)fminf(fmaxf(x_, 0.0f), (float)(WW - 1));
        int cell = bn * HW + ym * WW + xm;

        // Warp-aggregated atomicMax: p is monotonic with lane within a warp,
        // so the highest lane of each same-cell peer group carries the max p.
        unsigned peers  = __match_any_sync(0xffffffffu, cell);
        int      leader = 31 - __clz(peers);
        if (lane == leader) atomicMax(&g_winner[cell], p);

        g_scratch[bn * PP + p] = make_float2(depth, vilu);  // coalesced 8B
    }
}

// ---------------- kernel 3: per-cell gather + output write -----------------
__global__ void __launch_bounds__(256)
k_cells(float* __restrict__ out)   // (bsn, 2, H, W)
{
    int c = blockIdx.x * blockDim.x + threadIdx.x;
    if (c >= BSN * HW) return;
    int bn   = c / HW;
    int cell = c - bn * HW;
    int w = g_winner[c];
    float d = 0.0f, il = 0.0f;
    if (w >= 0) {
        float2 v = g_scratch[bn * PP + w];
        d  = v.x * (1.0f / (float)(BEV / 2));      // depth / 100
        il = log1pf(v.y) * 0.18033688011112042f;   // log1p(x) / ln(256)
    }
    out[(bn * 2    ) * HW + cell] = d;
    out[(bn * 2 + 1) * HW + cell] = il;
}

// ---------------- launch ----------------------------------------------------
extern "C" void kernel_launch(void* const* d_in, const int* in_sizes, int n_in,
                              void* d_out, int out_size)
{
    const float* pc = (const float*)d_in[0];  // pcloud
    const float* E  = (const float*)d_in[1];  // extrinsics
    const float* K  = (const float*)d_in[2];  // intrinsics
    const float* V  = (const float*)d_in[3];  // view
    float* out = (float*)d_out;

    k_init_winner<<<(BSN * HW + 1023) / 1024, 1024>>>();
    k_precompute<<<1, 128>>>(E, K, V);
    k_points<<<(BB * PP) / 256, 256>>>(pc);
    k_cells<<<(BSN * HW + 255) / 256, 256>>>(out);
}